// round 11
// baseline (speedup 1.0000x reference)
#include <cuda_runtime.h>
#include <math.h>
#include <stdint.h>

// Problem constants
#define T_TOK 8192
#define HD    1024
#define ID    2816
#define NE    8
#define NS    16384
#define RB    1024

// GEMM tiling
#define BN 128
#define BKT 32
#define ASTRIDE 40           // permuted A row: 32 data + 8 pad (8gq+2qq banks, conflict-free)
#define BROW 264             // repacked B row: 256 data + 8 pad
#define STAGES 3

// gateup: BM=128. stage floats: A 128*40=5120, Bg 16*264=4224, Bu 4224
#define GU_BM   128
#define GU_AS   5120
#define GU_BG   4224
#define GU_STG  (GU_AS + 2*GU_BG)          // 13568
#define GU_SMEM (STAGES*GU_STG*4)          // 162816 B

// down: BM=256. stage floats: A 256*40=10240, B 4224
#define DN_BM   256
#define DN_AS   10240
#define DN_STG  (DN_AS + 4224)             // 14464
#define DN_SMEM (STAGES*DN_STG*4)          // 173568 B

// ---------------- scratch ----------------
__device__ float g_Hg [(size_t)NS*ID];      // silu(gate)*up, tf32, PERMUTED rows
__device__ float g_Y  [(size_t)NS*HD];
__device__ float g_Xc [(size_t)T_TOK*HD];   // tf32(x), PERMUTED rows
__device__ float g_Wgc[(size_t)NE*HD*ID];   // tf32(Wg), row-pair interleaved
__device__ float g_Wuc[(size_t)NE*HD*ID];
__device__ float g_Wdc[(size_t)NE*ID*HD];
__device__ float g_topw[T_TOK*2];
__device__ int   g_topidx[T_TOK*2];
__device__ int   g_slot[T_TOK*2];
__device__ int   g_tok[NS];
__device__ int   g_cnt[NE];
__device__ int   g_off[NE];
__device__ float g_probpart[RB*NE];

// ---------------- helpers ----------------
__device__ __forceinline__ unsigned f2tf(float x){
    unsigned r; asm("cvt.rna.tf32.f32 %0, %1;" : "=r"(r) : "f"(x)); return r;
}
__device__ __forceinline__ float4 cvt4(float4 v){
    float4 o;
    o.x = __uint_as_float(f2tf(v.x));
    o.y = __uint_as_float(f2tf(v.y));
    o.z = __uint_as_float(f2tf(v.z));
    o.w = __uint_as_float(f2tf(v.w));
    return o;
}
__device__ __forceinline__ void mma8(float* d, const unsigned* a, const unsigned* b){
    asm volatile(
        "mma.sync.aligned.m16n8k8.row.col.f32.tf32.tf32.f32 "
        "{%0,%1,%2,%3}, {%4,%5,%6,%7}, {%8,%9}, {%0,%1,%2,%3};\n"
        : "+f"(d[0]), "+f"(d[1]), "+f"(d[2]), "+f"(d[3])
        : "r"(a[0]), "r"(a[1]), "r"(a[2]), "r"(a[3]), "r"(b[0]), "r"(b[1]));
}
__device__ __forceinline__ uint32_t smem_u32(const void* p){
    uint32_t a;
    asm("{ .reg .u64 t; cvta.to.shared.u64 t, %1; cvt.u32.u64 %0, t; }" : "=r"(a) : "l"(p));
    return a;
}
__device__ __forceinline__ void cpa16(uint32_t d, const float* s){
    asm volatile("cp.async.cg.shared.global [%0], [%1], 16;" :: "r"(d), "l"(s) : "memory");
}
#define CP_COMMIT() asm volatile("cp.async.commit_group;" ::: "memory")
#define CP_WAIT1()  asm volatile("cp.async.wait_group 1;" ::: "memory")

// ---------------- K1: cvt + repack (+ counter init) ----------------
// x rows: each 8-group [v0..v7] -> [v0,v4,v1,v5,v2,v6,v3,v7]
// W mats: k-rows (8g+j, 8g+j+4) interleaved elementwise into row (4g+j) of width 2N
__global__ void k_cvt_all(const float* __restrict__ x,
                          const float* __restrict__ wg,
                          const float* __restrict__ wu,
                          const float* __restrict__ wd){
    if (blockIdx.x == 0 && threadIdx.x < NE) g_cnt[threadIdx.x] = 0;

    const long nXop = (long)T_TOK * (HD/8);                 // 1,048,576
    const long nWop = (long)NE * HD * ID / 8;               // 2,883,584 per mat
    const long total = nXop + 3*nWop;
    long st = (long)gridDim.x * 256;
    for (long i = (long)blockIdx.x*256 + threadIdx.x; i < total; i += st){
        if (i < nXop){
            long base = i * 8;                              // row*HD + g*8
            float4 a = cvt4(*(const float4*)(x + base));
            float4 b = cvt4(*(const float4*)(x + base + 4));
            float4 o0 = make_float4(a.x, b.x, a.y, b.y);
            float4 o1 = make_float4(a.z, b.z, a.w, b.w);
            *(float4*)(g_Xc + base)     = o0;
            *(float4*)(g_Xc + base + 4) = o1;
        } else {
            long j = i - nXop;
            const float* src; float* dst; int K, N;
            if (j < nWop){ src = wg; dst = g_Wgc; K = HD; N = ID; }
            else if (j < 2*nWop){ j -= nWop; src = wu; dst = g_Wuc; K = HD; N = ID; }
            else { j -= 2*nWop; src = wd; dst = g_Wdc; K = ID; N = HD; }
            int n4pm = N/4;
            long perE = (long)K * N / 8;
            int e = (int)(j / perE);
            long r = j - (long)e * perE;
            int g  = (int)(r / (4*n4pm));
            int r2 = (int)(r - (long)g * (4*n4pm));
            int jj = r2 / n4pm;
            int n4 = r2 - jj * n4pm;
            const float* s0 = src + (size_t)e*K*N + (size_t)(8*g + jj)*N + n4*4;
            float4 a = cvt4(*(const float4*)(s0));
            float4 b = cvt4(*(const float4*)(s0 + 4*N));
            float* d0 = dst + (size_t)e*K*N + (size_t)(4*g + jj)*2*N + n4*8;
            *(float4*)(d0)     = make_float4(a.x, b.x, a.y, b.y);
            *(float4*)(d0 + 4) = make_float4(a.z, b.z, a.w, b.w);
        }
    }
}

// ---------------- K2: router ----------------
__global__ __launch_bounds__(256) void k_router(const float* __restrict__ x,
                                                const float* __restrict__ Wr){
    __shared__ float sp[8][8];
    __shared__ int   shc[8];
    int tid = threadIdx.x, wid = tid >> 5, lane = tid & 31;
    if (tid < 8) shc[tid] = 0;
    __syncthreads();

    int t = blockIdx.x * 8 + wid;
    const float* xr = x + (size_t)t * HD;
    float acc[8];
    #pragma unroll
    for (int e = 0; e < 8; e++) acc[e] = 0.f;

    for (int h0 = 0; h0 < HD; h0 += 32){
        float xv = xr[h0 + lane];
        const float4* w = (const float4*)(Wr + (size_t)(h0 + lane) * NE);
        float4 w0 = w[0], w1 = w[1];
        acc[0] += xv*w0.x; acc[1] += xv*w0.y; acc[2] += xv*w0.z; acc[3] += xv*w0.w;
        acc[4] += xv*w1.x; acc[5] += xv*w1.y; acc[6] += xv*w1.z; acc[7] += xv*w1.w;
    }
    #pragma unroll
    for (int e = 0; e < 8; e++)
        #pragma unroll
        for (int o = 16; o > 0; o >>= 1)
            acc[e] += __shfl_xor_sync(0xffffffffu, acc[e], o);

    if (lane == 0){
        float mx = acc[0];
        #pragma unroll
        for (int e = 1; e < 8; e++) mx = fmaxf(mx, acc[e]);
        float p[8], s = 0.f;
        #pragma unroll
        for (int e = 0; e < 8; e++){ p[e] = expf(acc[e] - mx); s += p[e]; }
        float inv = 1.f / s;
        #pragma unroll
        for (int e = 0; e < 8; e++){ p[e] *= inv; sp[wid][e] = p[e]; }
        int i0 = 0; float v0 = p[0];
        #pragma unroll
        for (int e = 1; e < 8; e++) if (p[e] > v0){ v0 = p[e]; i0 = e; }
        int i1 = -1; float v1 = -1.f;
        #pragma unroll
        for (int e = 0; e < 8; e++) if (e != i0 && p[e] > v1){ v1 = p[e]; i1 = e; }
        float rs = 1.f / (v0 + v1 + 1e-9f);
        g_topw[2*t]   = v0 * rs;  g_topw[2*t+1]   = v1 * rs;
        g_topidx[2*t] = i0;       g_topidx[2*t+1] = i1;
        atomicAdd(&shc[i0], 1);   atomicAdd(&shc[i1], 1);
    }
    __syncthreads();
    if (tid < 8){
        float s = 0.f;
        #pragma unroll
        for (int w = 0; w < 8; w++) s += sp[w][tid];
        g_probpart[blockIdx.x * 8 + tid] = s;
        atomicAdd(&g_cnt[tid], shc[tid]);
    }
}

// ---------------- K3: offsets + aux loss + slot assignment (1 block) ----------
__global__ __launch_bounds__(256) void k_route_setup(float* __restrict__ out, int out_size){
    __shared__ float sp2[32][8];
    __shared__ float pm[8];
    __shared__ int   s_off[8];
    __shared__ int   sc[8];
    int tid = threadIdx.x;
    int e = tid & 7, ch = tid >> 3;
    float s = 0.f;
    for (int j = ch * 32; j < ch * 32 + 32; j++) s += g_probpart[j * 8 + e];
    sp2[ch][e] = s;
    __syncthreads();
    if (tid < 8){
        float ss = 0.f;
        for (int c = 0; c < 32; c++) ss += sp2[c][tid];
        pm[tid] = ss / (float)T_TOK;
        sc[tid] = 0;
    }
    __syncthreads();
    if (tid == 0){
        int o = 0;
        for (int i = 0; i < NE; i++){ s_off[i] = o; g_off[i] = o; o += g_cnt[i]; }
        float loss = 0.f;
        for (int i = 0; i < NE; i++) loss += pm[i] * ((float)g_cnt[i] / (float)T_TOK);
        loss *= (float)NE * 0.01f;
        if (out_size > T_TOK * HD) out[T_TOK * HD] = loss;
    }
    __syncthreads();
    for (int t = tid; t < T_TOK; t += 256){
        int e0 = g_topidx[2*t], e1 = g_topidx[2*t+1];
        int p0 = atomicAdd(&sc[e0], 1);
        int p1 = atomicAdd(&sc[e1], 1);
        int s0 = s_off[e0] + p0;
        int s1 = s_off[e1] + p1;
        g_slot[2*t] = s0;  g_slot[2*t+1] = s1;
        g_tok[s0] = t;     g_tok[s1] = t;
    }
}

// ---------------- K4: fused gate+up GEMM (vectorized frags) ----------
__global__ __launch_bounds__(256, 1) void k_gateup(){
    extern __shared__ float smf[];
    uint32_t sm_u = smem_u32(smf);

    int e = blockIdx.z;
    int cnt = g_cnt[e], off = g_off[e];
    int row0 = blockIdx.x * GU_BM;
    if (row0 >= cnt) return;
    int n0 = blockIdx.y * BN;
    const float* Wgp = g_Wgc + (size_t)e * HD * ID + n0*2;
    const float* Wup = g_Wuc + (size_t)e * HD * ID + n0*2;

    int tid = threadIdx.x, lane = tid & 31, wid = tid >> 5;
    int wm = wid & 1, wn = wid >> 1;           // 2x4 warps, 64x32 warp tiles
    int gq = lane >> 2, qq = lane & 3;

    // A loader: 4 rows/thread (permuted rows copied verbatim)
    int mA = tid >> 3, kq = (tid & 7) * 4;
    const float* arow[4];
    uint32_t adst[4];
    #pragma unroll
    for (int i = 0; i < 4; i++){
        int rl = mA + 32*i;
        int r = row0 + rl;
        int t = (r < cnt) ? g_tok[off + r] : 0;
        arow[i] = g_Xc + (size_t)t * HD + kq;
        adst[i] = (uint32_t)((rl*ASTRIDE + kq) * 4);
    }
    // B loader: 16 repacked rows (1024B each) per chunk, 4 chunks/thread
    int rB = tid >> 6, c64 = (tid & 63) * 4;
    uint32_t bdst[4];
    #pragma unroll
    for (int i = 0; i < 4; i++)
        bdst[i] = (uint32_t)(GU_AS*4 + ((rB + 4*i)*BROW + c64) * 4);

    float accg[4][4][4], accu[4][4][4];
    #pragma unroll
    for (int mt = 0; mt < 4; mt++)
        #pragma unroll
        for (int nt = 0; nt < 4; nt++)
            #pragma unroll
            for (int i = 0; i < 4; i++){ accg[mt][nt][i] = 0.f; accu[mt][nt][i] = 0.f; }

    const int KT = HD / BKT;     // 32

    #pragma unroll
    for (int p = 0; p < STAGES-1; p++){
        uint32_t sb = sm_u + (uint32_t)(p * GU_STG * 4);
        int ko = p * BKT;
        #pragma unroll
        for (int i = 0; i < 4; i++) cpa16(sb + adst[i], arow[i] + ko);
        #pragma unroll
        for (int i = 0; i < 4; i++){
            size_t so = (size_t)(p*16 + rB + 4*i) * (2*ID) + c64;
            cpa16(sb + bdst[i], Wgp + so);
            cpa16(sb + bdst[i] + GU_BG*4, Wup + so);
        }
        CP_COMMIT();
    }

    for (int kt = 0; kt < KT; kt++){
        CP_WAIT1();
        __syncthreads();
        int s = kt % STAGES;
        const float* Asc = smf + s*GU_STG;
        const float* Bgc = Asc + GU_AS;
        const float* Buc = Bgc + GU_BG;

        #pragma unroll
        for (int ks = 0; ks < 4; ks++){
            int k0 = ks * 8;
            unsigned af[4][4];
            #pragma unroll
            for (int mt = 0; mt < 4; mt++){
                int r = wm * 64 + mt * 16 + gq;
                float2 v0 = *(const float2*)&Asc[(r    )*ASTRIDE + k0 + 2*qq];
                float2 v1 = *(const float2*)&Asc[(r + 8)*ASTRIDE + k0 + 2*qq];
                af[mt][0] = __float_as_uint(v0.x);
                af[mt][1] = __float_as_uint(v1.x);
                af[mt][2] = __float_as_uint(v0.y);
                af[mt][3] = __float_as_uint(v1.y);
            }
            unsigned bfg[4][2], bfu[4][2];
            #pragma unroll
            for (int nt = 0; nt < 4; nt++){
                int c = wn * 32 + nt * 8 + gq;
                float2 g2 = *(const float2*)&Bgc[(ks*4 + qq)*BROW + c*2];
                float2 u2 = *(const float2*)&Buc[(ks*4 + qq)*BROW + c*2];
                bfg[nt][0] = __float_as_uint(g2.x);
                bfg[nt][1] = __float_as_uint(g2.y);
                bfu[nt][0] = __float_as_uint(u2.x);
                bfu[nt][1] = __float_as_uint(u2.y);
            }
            #pragma unroll
            for (int mt = 0; mt < 4; mt++)
                #pragma unroll
                for (int nt = 0; nt < 4; nt++){
                    mma8(accg[mt][nt], af[mt], bfg[nt]);
                    mma8(accu[mt][nt], af[mt], bfu[nt]);
                }
        }

        int kp = kt + STAGES - 1;
        if (kp < KT){
            uint32_t sb = sm_u + (uint32_t)((kp % STAGES) * GU_STG * 4);
            int ko = kp * BKT;
            #pragma unroll
            for (int i = 0; i < 4; i++) cpa16(sb + adst[i], arow[i] + ko);
            #pragma unroll
            for (int i = 0; i < 4; i++){
                size_t so = (size_t)(kp*16 + rB + 4*i) * (2*ID) + c64;
                cpa16(sb + bdst[i], Wgp + so);
                cpa16(sb + bdst[i] + GU_BG*4, Wup + so);
            }
        }
        CP_COMMIT();
    }

    // epilogue: silu(g)*u tf32-rounded, written in PERMUTED row layout
    int valid = cnt - row0;
    int pp0 = (qq < 2) ? (4*qq) : (4*qq - 7);      // perm of j=2qq; pp0+2 = perm of 2qq+1
    #pragma unroll
    for (int mt = 0; mt < 4; mt++){
        #pragma unroll
        for (int half = 0; half < 2; half++){
            int m = wm * 64 + mt * 16 + half * 8 + gq;
            if (m < valid){
                size_t slot = (size_t)(off + row0 + m);
                #pragma unroll
                for (int nt = 0; nt < 4; nt++){
                    int gB = n0 + wn * 32 + nt * 8;
                    float gg0 = accg[mt][nt][half * 2 + 0];
                    float gg1 = accg[mt][nt][half * 2 + 1];
                    float uu0 = accu[mt][nt][half * 2 + 0];
                    float uu1 = accu[mt][nt][half * 2 + 1];
                    float h0 = gg0 / (1.f + expf(-gg0)) * uu0;
                    float h1 = gg1 / (1.f + expf(-gg1)) * uu1;
                    g_Hg[slot * ID + gB + pp0]     = __uint_as_float(f2tf(h0));
                    g_Hg[slot * ID + gB + pp0 + 2] = __uint_as_float(f2tf(h1));
                }
            }
        }
    }
}

// ---------------- K5: down GEMM (BM=256, 64x64 warp tiles, vectorized frags) ----
__global__ __launch_bounds__(256, 1) void k_down(){
    extern __shared__ float smf[];
    uint32_t sm_u = smem_u32(smf);

    int e = blockIdx.z;
    int cnt = g_cnt[e], off = g_off[e];
    int row0 = blockIdx.x * DN_BM;
    if (row0 >= cnt) return;
    int n0 = blockIdx.y * BN;
    const float* Wp = g_Wdc + (size_t)e * ID * HD + n0*2;

    int tid = threadIdx.x, lane = tid & 31, wid = tid >> 5;
    int wm = wid & 3, wn = wid >> 2;           // 4x2 warps, 64x64 warp tiles
    int gq = lane >> 2, qq = lane & 3;

    int mA = tid >> 3, kq = (tid & 7) * 4;
    const float* arow[8];
    uint32_t adst[8];
    #pragma unroll
    for (int i = 0; i < 8; i++){
        int rl = mA + 32*i;
        int s = off + row0 + rl; if (s >= NS) s = NS - 1;
        arow[i] = g_Hg + (size_t)s * ID + kq;
        adst[i] = (uint32_t)((rl*ASTRIDE + kq) * 4);
    }
    int rB = tid >> 6, c64 = (tid & 63) * 4;
    uint32_t bdst[4];
    #pragma unroll
    for (int i = 0; i < 4; i++)
        bdst[i] = (uint32_t)(DN_AS*4 + ((rB + 4*i)*BROW + c64) * 4);

    float acc[4][8][4];
    #pragma unroll
    for (int mt = 0; mt < 4; mt++)
        #pragma unroll
        for (int nt = 0; nt < 8; nt++)
            #pragma unroll
            for (int i = 0; i < 4; i++) acc[mt][nt][i] = 0.f;

    const int KT = ID / BKT;      // 88

    #pragma unroll
    for (int p = 0; p < STAGES-1; p++){
        uint32_t sb = sm_u + (uint32_t)(p * DN_STG * 4);
        int ko = p * BKT;
        #pragma unroll
        for (int i = 0; i < 8; i++) cpa16(sb + adst[i], arow[i] + ko);
        #pragma unroll
        for (int i = 0; i < 4; i++)
            cpa16(sb + bdst[i], Wp + (size_t)(p*16 + rB + 4*i) * (2*HD) + c64);
        CP_COMMIT();
    }

    for (int kt = 0; kt < KT; kt++){
        CP_WAIT1();
        __syncthreads();
        int s = kt % STAGES;
        const float* Asc = smf + s*DN_STG;
        const float* Bsc = Asc + DN_AS;

        #pragma unroll
        for (int ks = 0; ks < 4; ks++){
            int k0 = ks * 8;
            unsigned af[4][4];
            #pragma unroll
            for (int mt = 0; mt < 4; mt++){
                int r = wm * 64 + mt * 16 + gq;
                float2 v0 = *(const float2*)&Asc[(r    )*ASTRIDE + k0 + 2*qq];
                float2 v1 = *(const float2*)&Asc[(r + 8)*ASTRIDE + k0 + 2*qq];
                af[mt][0] = __float_as_uint(v0.x);
                af[mt][1] = __float_as_uint(v1.x);
                af[mt][2] = __float_as_uint(v0.y);
                af[mt][3] = __float_as_uint(v1.y);
            }
            unsigned bf[8][2];
            #pragma unroll
            for (int nt = 0; nt < 8; nt++){
                int c = wn * 64 + nt * 8 + gq;
                float2 b2 = *(const float2*)&Bsc[(ks*4 + qq)*BROW + c*2];
                bf[nt][0] = __float_as_uint(b2.x);
                bf[nt][1] = __float_as_uint(b2.y);
            }
            #pragma unroll
            for (int mt = 0; mt < 4; mt++)
                #pragma unroll
                for (int nt = 0; nt < 8; nt++)
                    mma8(acc[mt][nt], af[mt], bf[nt]);
        }

        int kp = kt + STAGES - 1;
        if (kp < KT){
            uint32_t sb = sm_u + (uint32_t)((kp % STAGES) * DN_STG * 4);
            int ko = kp * BKT;
            #pragma unroll
            for (int i = 0; i < 8; i++) cpa16(sb + adst[i], arow[i] + ko);
            #pragma unroll
            for (int i = 0; i < 4; i++)
                cpa16(sb + bdst[i], Wp + (size_t)(kp*16 + rB + 4*i) * (2*HD) + c64);
        }
        CP_COMMIT();
    }

    int valid = cnt - row0;
    #pragma unroll
    for (int mt = 0; mt < 4; mt++){
        #pragma unroll
        for (int half = 0; half < 2; half++){
            int m = wm * 64 + mt * 16 + half * 8 + gq;
            if (m < valid){
                size_t slot = (size_t)(off + row0 + m);
                #pragma unroll
                for (int nt = 0; nt < 8; nt++){
                    int c = n0 + wn * 64 + nt * 8 + qq * 2;
                    *(float2*)&g_Y[slot * HD + c] =
                        make_float2(acc[mt][nt][half*2+0], acc[mt][nt][half*2+1]);
                }
            }
        }
    }
}

// ---------------- K6: weighted combine ----------------
__global__ void k_combine(float* __restrict__ out){
    int t = blockIdx.x;
    float w0 = g_topw[2*t], w1 = g_topw[2*t+1];
    const float4* y0 = (const float4*)(g_Y + (size_t)g_slot[2*t]   * HD);
    const float4* y1 = (const float4*)(g_Y + (size_t)g_slot[2*t+1] * HD);
    float4* o = (float4*)(out + (size_t)t * HD);
    int i = threadIdx.x;
    float4 a = y0[i], b = y1[i];
    o[i] = make_float4(w0*a.x + w1*b.x, w0*a.y + w1*b.y,
                       w0*a.z + w1*b.z, w0*a.w + w1*b.w);
}

// ---------------- launch ----------------
extern "C" void kernel_launch(void* const* d_in, const int* in_sizes, int n_in,
                              void* d_out, int out_size){
    const float* x  = (const float*)d_in[0];
    const float* Wr = (const float*)d_in[1];
    const float* Wg = (const float*)d_in[2];
    const float* Wu = (const float*)d_in[3];
    const float* Wd = (const float*)d_in[4];
    float* out = (float*)d_out;

    cudaFuncSetAttribute(k_gateup, cudaFuncAttributeMaxDynamicSharedMemorySize, GU_SMEM);
    cudaFuncSetAttribute(k_down,   cudaFuncAttributeMaxDynamicSharedMemorySize, DN_SMEM);

    k_cvt_all<<<8192, 256>>>(x, Wg, Wu, Wd);                 // #1 (also inits counters)
    k_router<<<RB, 256>>>(x, Wr);                            // #2
    k_route_setup<<<1, 256>>>(out, out_size);                // #3
    dim3 g1(T_TOK / GU_BM, ID / BN, NE);                     // (64, 22, 8)
    k_gateup<<<g1, 256, GU_SMEM>>>();                        // #4  <- ncu capture slot
    dim3 g2(T_TOK / DN_BM, HD / BN, NE);                     // (32, 8, 8)
    k_down<<<g2, 256, DN_SMEM>>>();                          // #5
    k_combine<<<T_TOK, 256>>>(out);                          // #6
}